// round 1
// baseline (speedup 1.0000x reference)
#include <cuda_runtime.h>
#include <math.h>

#define T_DIM 4
#define C_DIM 13
#define H_DIM 361
#define W_DIM 720
#define HW    (H_DIM * W_DIM)        /* 259920  */
#define CHW   (C_DIM * HW)           /* 3378960 */
#define N2    (T_DIM * HW)           /* 1039680 */
#define W4    (W_DIM / 4)            /* 180     */
#define N4    (T_DIM * H_DIM * W4)   /* 259920  */

// Scratch (static device globals: allowed; no runtime allocation)
__device__ float  g_Up[N2];
__device__ float  g_Vp[N2];
__device__ float  g_Ut[N2];
__device__ float  g_Vt[N2];
__device__ float  g_lsp[N2];
__device__ float  g_lst[N2];
__device__ float  g_adx[H_DIM];
__device__ float  g_dp[C_DIM];
__device__ double g_acc;

// ---------------------------------------------------------------------------
// Setup: per-row adx LUT (accurate cos near poles via double), dp LUT, zero acc
// ---------------------------------------------------------------------------
__global__ void setup_k(const float* __restrict__ lat,
                        const float* __restrict__ lev,
                        const float* __restrict__ dxp)
{
    int i = threadIdx.x;
    if (i < H_DIM) {
        // Replicate JAX float32 sequence: ang = (lat * f32(pi)) / f32(180)
        float ang = (lat[i] * (float)M_PI) / 180.0f;
        // Accurate cos of the f32 angle (fast-math __cosf would destroy the
        // tiny pole value that dominates the loss)
        float cv  = (float)cos((double)ang);
        float mpl = (float)(M_PI * 6371000.0 / 180.0);   // m per deg lat (f32)
        float m_per_lon = mpl * cv;                       // f32 mul, like JAX
        g_adx[i] = dxp[0] * m_per_lon;                    // f32 mul, like JAX
    }
    int j = i - H_DIM;
    if (j >= 0 && j < C_DIM) {
        float d;
        if (j == 0)            d = (lev[1] - lev[0]) * 100.0f;
        else if (j == C_DIM-1) d = (lev[C_DIM-1] - lev[C_DIM-2]) * 100.0f;
        else                   d = (lev[j+1] - lev[j-1]) * 50.0f;
        g_dp[j] = d;
    }
    if (i == 511) g_acc = 0.0;
}

// ---------------------------------------------------------------------------
// Kernel A: channel-weighted reduction U=Σ dp_c u_c, V=Σ dp_c v_c (float4),
// plus log(sp) fields. Streams the four 54 MB tensors exactly once.
// ---------------------------------------------------------------------------
__global__ void __launch_bounds__(256) reduce_k(
    const float* __restrict__ up, const float* __restrict__ vp,
    const float* __restrict__ ut, const float* __restrict__ vt,
    const float* __restrict__ spp, const float* __restrict__ spt)
{
    int i = blockIdx.x * 256 + threadIdx.x;
    if (i >= N4) return;
    int w4 = i % W4;
    int hh = (i / W4) % H_DIM;
    int t  = i / (W4 * H_DIM);
    int base2 = t * HW  + hh * W_DIM + 4 * w4;
    int base5 = t * CHW + hh * W_DIM + 4 * w4;

    float dpl[C_DIM];
    #pragma unroll
    for (int c = 0; c < C_DIM; ++c) dpl[c] = g_dp[c];

    float4 Up = make_float4(0.f, 0.f, 0.f, 0.f);
    float4 Vp = Up, Ut = Up, Vt = Up;

    #pragma unroll
    for (int c = 0; c < C_DIM; ++c) {
        int off = base5 + c * HW;
        float dp = dpl[c];
        float4 a = __ldg((const float4*)(up + off));
        float4 b = __ldg((const float4*)(vp + off));
        float4 e = __ldg((const float4*)(ut + off));
        float4 f = __ldg((const float4*)(vt + off));
        Up.x = fmaf(dp, a.x, Up.x); Up.y = fmaf(dp, a.y, Up.y);
        Up.z = fmaf(dp, a.z, Up.z); Up.w = fmaf(dp, a.w, Up.w);
        Vp.x = fmaf(dp, b.x, Vp.x); Vp.y = fmaf(dp, b.y, Vp.y);
        Vp.z = fmaf(dp, b.z, Vp.z); Vp.w = fmaf(dp, b.w, Vp.w);
        Ut.x = fmaf(dp, e.x, Ut.x); Ut.y = fmaf(dp, e.y, Ut.y);
        Ut.z = fmaf(dp, e.z, Ut.z); Ut.w = fmaf(dp, e.w, Ut.w);
        Vt.x = fmaf(dp, f.x, Vt.x); Vt.y = fmaf(dp, f.y, Vt.y);
        Vt.z = fmaf(dp, f.z, Vt.z); Vt.w = fmaf(dp, f.w, Vt.w);
    }

    *(float4*)(g_Up + base2) = Up;
    *(float4*)(g_Vp + base2) = Vp;
    *(float4*)(g_Ut + base2) = Ut;
    *(float4*)(g_Vt + base2) = Vt;

    float4 s = __ldg((const float4*)(spp + base2));
    float4 l;
    l.x = logf(s.x); l.y = logf(s.y); l.z = logf(s.z); l.w = logf(s.w);
    *(float4*)(g_lsp + base2) = l;

    s = __ldg((const float4*)(spt + base2));
    l.x = logf(s.x); l.y = logf(s.y); l.z = logf(s.z); l.w = logf(s.w);
    *(float4*)(g_lst + base2) = l;
}

// ---------------------------------------------------------------------------
// Kernel B: residual stencil for both sources + squared diff + reduction
// ---------------------------------------------------------------------------
__device__ __forceinline__ float residual_one(
    const float* __restrict__ ls, const float* __restrict__ Uf,
    const float* __restrict__ Vf, const float* __restrict__ sp,
    int i, int t, int hh, int w, float dtv, float adx, float ady)
{
    float ls0 = ls[i];
    float U0  = Uf[i];
    float V0  = Vf[i];

    // time derivative of log(sp)
    float dls_dt;
    if (t == 0)              dls_dt = (ls[i + HW] - ls0) / dtv;
    else if (t == T_DIM - 1) dls_dt = (ls0 - ls[i - HW]) / dtv;
    else                     dls_dt = (ls[i + HW] - ls[i - HW]) / (2.0f * dtv);

    // lon derivatives (d/dx)
    float dUdx, dlsx;
    if (w == 0)              { dUdx = Uf[i+1] - U0;              dlsx = ls[i+1] - ls0; }
    else if (w == W_DIM - 1) { dUdx = U0 - Uf[i-1];              dlsx = ls0 - ls[i-1]; }
    else                     { dUdx = (Uf[i+1] - Uf[i-1])*0.5f;  dlsx = (ls[i+1] - ls[i-1])*0.5f; }
    dUdx /= adx;
    dlsx /= adx;

    // lat derivatives (d/dy)
    float dVdy, dlsy;
    if (hh == 0)             { dVdy = Vf[i+W_DIM] - V0;                 dlsy = ls[i+W_DIM] - ls0; }
    else if (hh == H_DIM-1)  { dVdy = V0 - Vf[i-W_DIM];                 dlsy = ls0 - ls[i-W_DIM]; }
    else                     { dVdy = (Vf[i+W_DIM] - Vf[i-W_DIM])*0.5f; dlsy = (ls[i+W_DIM] - ls[i-W_DIM])*0.5f; }
    dVdy /= ady;
    dlsy /= ady;

    float sp0 = sp[i];
    float integ = (dUdx + dVdy + dlsx * U0 + dlsy * V0) / sp0;
    return dls_dt + integ;
}

__global__ void __launch_bounds__(256) residual_k(
    const float* __restrict__ spp, const float* __restrict__ spt,
    const float* __restrict__ dtp, const float* __restrict__ dyp)
{
    int i = blockIdx.x * 256 + threadIdx.x;
    float val = 0.0f;
    if (i < N2) {
        int w  = i % W_DIM;
        int hh = (i / W_DIM) % H_DIM;
        int t  = i / HW;
        float dtv = dtp[0];
        float mpl = (float)(M_PI * 6371000.0 / 180.0);
        float ady = dyp[0] * mpl;
        float adx = g_adx[hh];

        float rp = residual_one(g_lsp, g_Up, g_Vp, spp, i, t, hh, w, dtv, adx, ady);
        float rt = residual_one(g_lst, g_Ut, g_Vt, spt, i, t, hh, w, dtv, adx, ady);
        float d  = rp - rt;
        val = d * d;
    }

    // warp reduce
    #pragma unroll
    for (int o = 16; o > 0; o >>= 1)
        val += __shfl_down_sync(0xffffffffu, val, o);

    __shared__ float sw[8];
    int lane = threadIdx.x & 31;
    int wid  = threadIdx.x >> 5;
    if (lane == 0) sw[wid] = val;
    __syncthreads();
    if (wid == 0) {
        float v = (lane < 8) ? sw[lane] : 0.0f;
        #pragma unroll
        for (int o = 4; o > 0; o >>= 1)
            v += __shfl_down_sync(0xffffffffu, v, o);
        if (lane == 0) atomicAdd(&g_acc, (double)v);
    }
}

__global__ void finalize_k(float* out)
{
    out[0] = (float)(g_acc / (double)N2);
}

// ---------------------------------------------------------------------------
extern "C" void kernel_launch(void* const* d_in, const int* in_sizes, int n_in,
                              void* d_out, int out_size)
{
    const float* pu  = (const float*)d_in[0];
    const float* pv  = (const float*)d_in[1];
    const float* psp = (const float*)d_in[2];
    const float* tu  = (const float*)d_in[3];
    const float* tv  = (const float*)d_in[4];
    const float* tsp = (const float*)d_in[5];
    const float* lat = (const float*)d_in[6];
    const float* lev = (const float*)d_in[7];
    const float* dt  = (const float*)d_in[8];
    const float* dx  = (const float*)d_in[9];
    const float* dy  = (const float*)d_in[10];

    setup_k<<<1, 512>>>(lat, lev, dx);
    reduce_k<<<(N4 + 255) / 256, 256>>>(pu, pv, tu, tv, psp, tsp);
    residual_k<<<(N2 + 255) / 256, 256>>>(psp, tsp, dt, dy);
    finalize_k<<<1, 1>>>((float*)d_out);
}

// round 2
// speedup vs baseline: 1.1374x; 1.1374x over previous
#include <cuda_runtime.h>
#include <math.h>

#define T_DIM 4
#define C_DIM 13
#define H_DIM 361
#define W_DIM 720
#define HW    (H_DIM * W_DIM)        /* 259920  */
#define CHW   (C_DIM * HW)           /* 3378960 */
#define N2    (T_DIM * HW)           /* 1039680 */
#define W4    (W_DIM / 4)            /* 180     */
#define N4    (T_DIM * H_DIM * W4)   /* 259920  */

// Scratch (static device globals: allowed; no runtime allocation)
__device__ float  g_Up[N2];
__device__ float  g_Vp[N2];
__device__ float  g_Ut[N2];
__device__ float  g_Vt[N2];
__device__ float  g_lsp[N2];
__device__ float  g_lst[N2];
__device__ float  g_adx[H_DIM];
__device__ double g_acc;
__device__ unsigned int g_bcount = 0;   // self-resetting via atomicInc wrap

// ---------------------------------------------------------------------------
// Kernel A: blockIdx.y selects work:
//   y = 0..3 : channel-weighted reduction of one tensor (13 float4 loads/thr)
//   y = 4    : log(sp) for both sources
// Block (0,0) additionally builds the adx LUT (accurate pole cos) and zeroes
// the accumulator — hidden under the memory stream.
// ---------------------------------------------------------------------------
__global__ void __launch_bounds__(256) reduce_k(
    const float* __restrict__ up, const float* __restrict__ vp,
    const float* __restrict__ ut, const float* __restrict__ vt,
    const float* __restrict__ spp, const float* __restrict__ spt,
    const float* __restrict__ lat, const float* __restrict__ lev,
    const float* __restrict__ dxp)
{
    const int ten = blockIdx.y;

    if (blockIdx.x == 0 && ten == 0) {
        for (int r = threadIdx.x; r < H_DIM; r += 256) {
            // Replicate JAX f32 sequence: ang = (lat * f32(pi)) / f32(180)
            float ang = (lat[r] * (float)M_PI) / 180.0f;
            // Accurate cos of the f32 angle (pole rows dominate the loss;
            // fast-math cos would destroy the ~4e-8 pole value)
            float cv  = (float)cos((double)ang);
            float mpl = (float)(M_PI * 6371000.0 / 180.0);
            g_adx[r]  = dxp[0] * (mpl * cv);
        }
        if (threadIdx.x == 0) g_acc = 0.0;
    }

    int i = blockIdx.x * 256 + threadIdx.x;
    if (i >= N4) return;
    int w4 = i % W4;
    int hh = (i / W4) % H_DIM;
    int t  = i / (W4 * H_DIM);
    int base2 = t * HW  + hh * W_DIM + 4 * w4;

    if (ten == 4) {
        float4 s = __ldg((const float4*)(spp + base2));
        float4 l;
        l.x = logf(s.x); l.y = logf(s.y); l.z = logf(s.z); l.w = logf(s.w);
        *(float4*)(g_lsp + base2) = l;
        s = __ldg((const float4*)(spt + base2));
        l.x = logf(s.x); l.y = logf(s.y); l.z = logf(s.z); l.w = logf(s.w);
        *(float4*)(g_lst + base2) = l;
        return;
    }

    const float* __restrict__ src;
    float* dst;
    switch (ten) {
        case 0: src = up; dst = g_Up; break;
        case 1: src = vp; dst = g_Vp; break;
        case 2: src = ut; dst = g_Ut; break;
        default: src = vt; dst = g_Vt; break;
    }

    // delta-sigma pressure weights (constant per channel), f32 math like JAX
    float dpl[C_DIM];
    {
        float l0 = __ldg(lev + 0), l1 = __ldg(lev + 1);
        dpl[0] = (l1 - l0) * 100.0f;
        #pragma unroll
        for (int c = 1; c < C_DIM - 1; ++c)
            dpl[c] = (__ldg(lev + c + 1) - __ldg(lev + c - 1)) * 50.0f;
        dpl[C_DIM-1] = (__ldg(lev + C_DIM - 1) - __ldg(lev + C_DIM - 2)) * 100.0f;
    }

    int base5 = t * CHW + hh * W_DIM + 4 * w4;
    float4 acc = make_float4(0.f, 0.f, 0.f, 0.f);
    #pragma unroll
    for (int c = 0; c < C_DIM; ++c) {
        float4 a = __ldg((const float4*)(src + base5 + c * HW));
        float dp = dpl[c];
        acc.x = fmaf(dp, a.x, acc.x);
        acc.y = fmaf(dp, a.y, acc.y);
        acc.z = fmaf(dp, a.z, acc.z);
        acc.w = fmaf(dp, a.w, acc.w);
    }
    *(float4*)(dst + base2) = acc;
}

// ---------------------------------------------------------------------------
// Kernel B: residual stencil for both sources + squared diff + reduction,
// with fused finalize (last-block-done writes the mean).
// ---------------------------------------------------------------------------
__device__ __forceinline__ float residual_one(
    const float* __restrict__ ls, const float* __restrict__ Uf,
    const float* __restrict__ Vf, const float* __restrict__ sp,
    int i, int t, int hh, int w, float dtv, float adx, float ady)
{
    float ls0 = ls[i];
    float U0  = Uf[i];
    float V0  = Vf[i];

    float dls_dt;
    if (t == 0)              dls_dt = (ls[i + HW] - ls0) / dtv;
    else if (t == T_DIM - 1) dls_dt = (ls0 - ls[i - HW]) / dtv;
    else                     dls_dt = (ls[i + HW] - ls[i - HW]) / (2.0f * dtv);

    float dUdx, dlsx;
    if (w == 0)              { dUdx = Uf[i+1] - U0;              dlsx = ls[i+1] - ls0; }
    else if (w == W_DIM - 1) { dUdx = U0 - Uf[i-1];              dlsx = ls0 - ls[i-1]; }
    else                     { dUdx = (Uf[i+1] - Uf[i-1])*0.5f;  dlsx = (ls[i+1] - ls[i-1])*0.5f; }
    dUdx /= adx;
    dlsx /= adx;

    float dVdy, dlsy;
    if (hh == 0)             { dVdy = Vf[i+W_DIM] - V0;                 dlsy = ls[i+W_DIM] - ls0; }
    else if (hh == H_DIM-1)  { dVdy = V0 - Vf[i-W_DIM];                 dlsy = ls0 - ls[i-W_DIM]; }
    else                     { dVdy = (Vf[i+W_DIM] - Vf[i-W_DIM])*0.5f; dlsy = (ls[i+W_DIM] - ls[i-W_DIM])*0.5f; }
    dVdy /= ady;
    dlsy /= ady;

    float integ = (dUdx + dVdy + dlsx * U0 + dlsy * V0) / sp[i];
    return dls_dt + integ;
}

__global__ void __launch_bounds__(256) residual_k(
    const float* __restrict__ spp, const float* __restrict__ spt,
    const float* __restrict__ dtp, const float* __restrict__ dyp,
    float* __restrict__ out)
{
    int i = blockIdx.x * 256 + threadIdx.x;
    float val = 0.0f;
    if (i < N2) {
        int w  = i % W_DIM;
        int hh = (i / W_DIM) % H_DIM;
        int t  = i / HW;
        float dtv = dtp[0];
        float mpl = (float)(M_PI * 6371000.0 / 180.0);
        float ady = dyp[0] * mpl;
        float adx = g_adx[hh];

        float rp = residual_one(g_lsp, g_Up, g_Vp, spp, i, t, hh, w, dtv, adx, ady);
        float rt = residual_one(g_lst, g_Ut, g_Vt, spt, i, t, hh, w, dtv, adx, ady);
        float d  = rp - rt;
        val = d * d;
    }

    #pragma unroll
    for (int o = 16; o > 0; o >>= 1)
        val += __shfl_down_sync(0xffffffffu, val, o);

    __shared__ float sw[8];
    __shared__ bool  isLast;
    int lane = threadIdx.x & 31;
    int wid  = threadIdx.x >> 5;
    if (lane == 0) sw[wid] = val;
    __syncthreads();
    if (wid == 0) {
        float v = (lane < 8) ? sw[lane] : 0.0f;
        #pragma unroll
        for (int o = 4; o > 0; o >>= 1)
            v += __shfl_down_sync(0xffffffffu, v, o);
        if (lane == 0) {
            atomicAdd(&g_acc, (double)v);
            __threadfence();
            unsigned done = atomicInc(&g_bcount, gridDim.x - 1);
            isLast = (done == gridDim.x - 1);   // wraps to 0 -> replay-safe
        }
    }
    __syncthreads();
    if (isLast && threadIdx.x == 0) {
        out[0] = (float)(g_acc / (double)N2);
    }
}

// ---------------------------------------------------------------------------
extern "C" void kernel_launch(void* const* d_in, const int* in_sizes, int n_in,
                              void* d_out, int out_size)
{
    const float* pu  = (const float*)d_in[0];
    const float* pv  = (const float*)d_in[1];
    const float* psp = (const float*)d_in[2];
    const float* tu  = (const float*)d_in[3];
    const float* tv  = (const float*)d_in[4];
    const float* tsp = (const float*)d_in[5];
    const float* lat = (const float*)d_in[6];
    const float* lev = (const float*)d_in[7];
    const float* dt  = (const float*)d_in[8];
    const float* dx  = (const float*)d_in[9];
    const float* dy  = (const float*)d_in[10];

    dim3 gridA((N4 + 255) / 256, 5);
    reduce_k<<<gridA, 256>>>(pu, pv, tu, tv, psp, tsp, lat, lev, dx);
    residual_k<<<(N2 + 255) / 256, 256>>>(psp, tsp, dt, dy, (float*)d_out);
}

// round 3
// speedup vs baseline: 1.3168x; 1.1578x over previous
#include <cuda_runtime.h>
#include <math.h>

#define T_DIM 4
#define C_DIM 13
#define H_DIM 361
#define W_DIM 720
#define HW    (H_DIM * W_DIM)        /* 259920  */
#define CHW   (C_DIM * HW)           /* 3378960 */
#define N2    (T_DIM * HW)           /* 1039680 */
#define W4    (W_DIM / 4)            /* 180     */
#define N4    (T_DIM * H_DIM * W4)   /* 259920  */

// Scratch (static device globals: allowed; no runtime allocation)
__device__ float  g_Up[N2];
__device__ float  g_Vp[N2];
__device__ float  g_Ut[N2];
__device__ float  g_Vt[N2];
__device__ float  g_lsp[N2];
__device__ float  g_lst[N2];
__device__ float  g_inv_adx[H_DIM];
__device__ float  g_consts[3];          // inv_dt, inv_2dt, inv_ady
__device__ double g_acc;
__device__ unsigned int g_bcount = 0;   // self-resetting via atomicInc wrap

__device__ __forceinline__ float4 LD4(const float* p) {
    return __ldg((const float4*)p);
}

// ---------------------------------------------------------------------------
// Kernel A: blockIdx.y selects work:
//   y = 0..3 : channel-weighted reduction of one tensor (13 float4 loads/thr)
//   y = 4    : log(sp) for both sources
// Block (0,0) additionally builds the reciprocal LUTs (accurate pole cos) and
// zeroes the accumulator — hidden under the memory stream.
// ---------------------------------------------------------------------------
__global__ void __launch_bounds__(256) reduce_k(
    const float* __restrict__ up, const float* __restrict__ vp,
    const float* __restrict__ ut, const float* __restrict__ vt,
    const float* __restrict__ spp, const float* __restrict__ spt,
    const float* __restrict__ lat, const float* __restrict__ lev,
    const float* __restrict__ dxp, const float* __restrict__ dtp,
    const float* __restrict__ dyp)
{
    const int ten = blockIdx.y;

    if (blockIdx.x == 0 && ten == 0) {
        for (int r = threadIdx.x; r < H_DIM; r += 256) {
            // Replicate JAX f32 sequence: ang = (lat * f32(pi)) / f32(180)
            float ang = (lat[r] * (float)M_PI) / 180.0f;
            // Accurate cos of the f32 angle (pole rows dominate the loss;
            // fast-math cos would destroy the ~4e-8 pole value)
            float cv  = (float)cos((double)ang);
            float mpl = (float)(M_PI * 6371000.0 / 180.0);
            float adx = dxp[0] * (mpl * cv);
            g_inv_adx[r] = (float)(1.0 / (double)adx);
        }
        if (threadIdx.x == 0) {
            float dtv = dtp[0];
            float mpl = (float)(M_PI * 6371000.0 / 180.0);
            float ady = dyp[0] * mpl;
            g_consts[0] = (float)(1.0 / (double)dtv);
            g_consts[1] = (float)(1.0 / (2.0 * (double)dtv));
            g_consts[2] = (float)(1.0 / (double)ady);
            g_acc = 0.0;
        }
    }

    int i = blockIdx.x * 256 + threadIdx.x;
    if (i >= N4) return;
    int w4 = i % W4;
    int hh = (i / W4) % H_DIM;
    int t  = i / (W4 * H_DIM);
    int base2 = t * HW  + hh * W_DIM + 4 * w4;

    if (ten == 4) {
        float4 s = LD4(spp + base2);
        float4 l;
        l.x = logf(s.x); l.y = logf(s.y); l.z = logf(s.z); l.w = logf(s.w);
        *(float4*)(g_lsp + base2) = l;
        s = LD4(spt + base2);
        l.x = logf(s.x); l.y = logf(s.y); l.z = logf(s.z); l.w = logf(s.w);
        *(float4*)(g_lst + base2) = l;
        return;
    }

    const float* __restrict__ src;
    float* dst;
    switch (ten) {
        case 0: src = up; dst = g_Up; break;
        case 1: src = vp; dst = g_Vp; break;
        case 2: src = ut; dst = g_Ut; break;
        default: src = vt; dst = g_Vt; break;
    }

    // delta-sigma pressure weights (constant per channel), f32 math like JAX
    float dpl[C_DIM];
    {
        dpl[0] = (__ldg(lev + 1) - __ldg(lev + 0)) * 100.0f;
        #pragma unroll
        for (int c = 1; c < C_DIM - 1; ++c)
            dpl[c] = (__ldg(lev + c + 1) - __ldg(lev + c - 1)) * 50.0f;
        dpl[C_DIM-1] = (__ldg(lev + C_DIM - 1) - __ldg(lev + C_DIM - 2)) * 100.0f;
    }

    int base5 = t * CHW + hh * W_DIM + 4 * w4;
    float4 acc = make_float4(0.f, 0.f, 0.f, 0.f);
    #pragma unroll
    for (int c = 0; c < C_DIM; ++c) {
        float4 a = LD4(src + base5 + c * HW);
        float dp = dpl[c];
        acc.x = fmaf(dp, a.x, acc.x);
        acc.y = fmaf(dp, a.y, acc.y);
        acc.z = fmaf(dp, a.z, acc.z);
        acc.w = fmaf(dp, a.w, acc.w);
    }
    *(float4*)(dst + base2) = acc;
}

// ---------------------------------------------------------------------------
// Kernel B: 4-wide vectorized residual stencil, no FP divides (reciprocal
// multiplies), fused block reduction + last-block finalize.
// ---------------------------------------------------------------------------
__device__ __forceinline__ float4 residual4(
    const float* __restrict__ ls, const float* __restrict__ Uf,
    const float* __restrict__ Vf, const float* __restrict__ sp,
    int base, int t, int hh, bool wlo, bool whi,
    float inv_dt, float inv_2dt, float inv_ady, float inv_adx)
{
    float4 c = LD4(ls + base);

    // ---- time derivative of log(sp) ----
    float4 r;
    if (t == 0) {
        float4 n = LD4(ls + base + HW);
        r.x = (n.x - c.x) * inv_dt; r.y = (n.y - c.y) * inv_dt;
        r.z = (n.z - c.z) * inv_dt; r.w = (n.w - c.w) * inv_dt;
    } else if (t == T_DIM - 1) {
        float4 p = LD4(ls + base - HW);
        r.x = (c.x - p.x) * inv_dt; r.y = (c.y - p.y) * inv_dt;
        r.z = (c.z - p.z) * inv_dt; r.w = (c.w - p.w) * inv_dt;
    } else {
        float4 n = LD4(ls + base + HW);
        float4 p = LD4(ls + base - HW);
        r.x = (n.x - p.x) * inv_2dt; r.y = (n.y - p.y) * inv_2dt;
        r.z = (n.z - p.z) * inv_2dt; r.w = (n.w - p.w) * inv_2dt;
    }

    // ---- lon derivatives: ls and U ----
    float lsl = wlo ? 0.0f : __ldg(ls + base - 1);
    float lsr = whi ? 0.0f : __ldg(ls + base + 4);
    float4 dlsx;
    dlsx.x = wlo ? (c.y - c.x) : (c.y - lsl) * 0.5f;
    dlsx.y = (c.z - c.x) * 0.5f;
    dlsx.z = (c.w - c.y) * 0.5f;
    dlsx.w = whi ? (c.w - c.z) : (lsr - c.z) * 0.5f;

    float4 u = LD4(Uf + base);
    float ul = wlo ? 0.0f : __ldg(Uf + base - 1);
    float ur = whi ? 0.0f : __ldg(Uf + base + 4);
    float4 dudx;
    dudx.x = wlo ? (u.y - u.x) : (u.y - ul) * 0.5f;
    dudx.y = (u.z - u.x) * 0.5f;
    dudx.z = (u.w - u.y) * 0.5f;
    dudx.w = whi ? (u.w - u.z) : (ur - u.z) * 0.5f;

    // ---- lat derivatives: ls and V ----
    float4 v = LD4(Vf + base);
    float4 dlsy, dvdy;
    if (hh == 0) {
        float4 ld = LD4(ls + base + W_DIM);
        float4 vd = LD4(Vf + base + W_DIM);
        dlsy.x = ld.x - c.x; dlsy.y = ld.y - c.y; dlsy.z = ld.z - c.z; dlsy.w = ld.w - c.w;
        dvdy.x = vd.x - v.x; dvdy.y = vd.y - v.y; dvdy.z = vd.z - v.z; dvdy.w = vd.w - v.w;
    } else if (hh == H_DIM - 1) {
        float4 lu = LD4(ls + base - W_DIM);
        float4 vu = LD4(Vf + base - W_DIM);
        dlsy.x = c.x - lu.x; dlsy.y = c.y - lu.y; dlsy.z = c.z - lu.z; dlsy.w = c.w - lu.w;
        dvdy.x = v.x - vu.x; dvdy.y = v.y - vu.y; dvdy.z = v.z - vu.z; dvdy.w = v.w - vu.w;
    } else {
        float4 ld = LD4(ls + base + W_DIM);
        float4 lu = LD4(ls + base - W_DIM);
        float4 vd = LD4(Vf + base + W_DIM);
        float4 vu = LD4(Vf + base - W_DIM);
        dlsy.x = (ld.x - lu.x) * 0.5f; dlsy.y = (ld.y - lu.y) * 0.5f;
        dlsy.z = (ld.z - lu.z) * 0.5f; dlsy.w = (ld.w - lu.w) * 0.5f;
        dvdy.x = (vd.x - vu.x) * 0.5f; dvdy.y = (vd.y - vu.y) * 0.5f;
        dvdy.z = (vd.z - vu.z) * 0.5f; dvdy.w = (vd.w - vu.w) * 0.5f;
    }

    // ---- combine: r + (dU/dx + dV/dy + U*dls/dx + V*dls/dy) / sp ----
    float4 s = LD4(sp + base);
    float4 out;
    {
        float ix = fmaf(u.x, dlsx.x, dudx.x) * inv_adx
                 + fmaf(v.x, dlsy.x, dvdy.x) * inv_ady;
        out.x = r.x + __fdividef(ix, s.x);
        float iy = fmaf(u.y, dlsx.y, dudx.y) * inv_adx
                 + fmaf(v.y, dlsy.y, dvdy.y) * inv_ady;
        out.y = r.y + __fdividef(iy, s.y);
        float iz = fmaf(u.z, dlsx.z, dudx.z) * inv_adx
                 + fmaf(v.z, dlsy.z, dvdy.z) * inv_ady;
        out.z = r.z + __fdividef(iz, s.z);
        float iw = fmaf(u.w, dlsx.w, dudx.w) * inv_adx
                 + fmaf(v.w, dlsy.w, dvdy.w) * inv_ady;
        out.w = r.w + __fdividef(iw, s.w);
    }
    return out;
}

__global__ void __launch_bounds__(256) residual_k(
    const float* __restrict__ spp, const float* __restrict__ spt,
    float* __restrict__ out)
{
    int i4 = blockIdx.x * 256 + threadIdx.x;
    float val = 0.0f;
    if (i4 < N4) {
        int w4 = i4 % W4;
        int hh = (i4 / W4) % H_DIM;
        int t  = i4 / (W4 * H_DIM);
        int base = t * HW + hh * W_DIM + 4 * w4;
        bool wlo = (w4 == 0), whi = (w4 == W4 - 1);

        float inv_dt  = g_consts[0];
        float inv_2dt = g_consts[1];
        float inv_ady = g_consts[2];
        float inv_adx = g_inv_adx[hh];

        float4 rp = residual4(g_lsp, g_Up, g_Vp, spp, base, t, hh, wlo, whi,
                              inv_dt, inv_2dt, inv_ady, inv_adx);
        float4 rt = residual4(g_lst, g_Ut, g_Vt, spt, base, t, hh, wlo, whi,
                              inv_dt, inv_2dt, inv_ady, inv_adx);
        float dx0 = rp.x - rt.x, dy0 = rp.y - rt.y;
        float dz0 = rp.z - rt.z, dw0 = rp.w - rt.w;
        val = dx0*dx0 + dy0*dy0 + dz0*dz0 + dw0*dw0;
    }

    #pragma unroll
    for (int o = 16; o > 0; o >>= 1)
        val += __shfl_down_sync(0xffffffffu, val, o);

    __shared__ float sw[8];
    __shared__ bool  isLast;
    int lane = threadIdx.x & 31;
    int wid  = threadIdx.x >> 5;
    if (lane == 0) sw[wid] = val;
    __syncthreads();
    if (wid == 0) {
        float v = (lane < 8) ? sw[lane] : 0.0f;
        #pragma unroll
        for (int o = 4; o > 0; o >>= 1)
            v += __shfl_down_sync(0xffffffffu, v, o);
        if (lane == 0) {
            atomicAdd(&g_acc, (double)v);
            __threadfence();
            unsigned done = atomicInc(&g_bcount, gridDim.x - 1);
            isLast = (done == gridDim.x - 1);   // wraps to 0 -> replay-safe
        }
    }
    __syncthreads();
    if (isLast && threadIdx.x == 0) {
        out[0] = (float)(g_acc / (double)N2);
    }
}

// ---------------------------------------------------------------------------
extern "C" void kernel_launch(void* const* d_in, const int* in_sizes, int n_in,
                              void* d_out, int out_size)
{
    const float* pu  = (const float*)d_in[0];
    const float* pv  = (const float*)d_in[1];
    const float* psp = (const float*)d_in[2];
    const float* tu  = (const float*)d_in[3];
    const float* tv  = (const float*)d_in[4];
    const float* tsp = (const float*)d_in[5];
    const float* lat = (const float*)d_in[6];
    const float* lev = (const float*)d_in[7];
    const float* dt  = (const float*)d_in[8];
    const float* dx  = (const float*)d_in[9];
    const float* dy  = (const float*)d_in[10];

    dim3 gridA((N4 + 255) / 256, 5);
    reduce_k<<<gridA, 256>>>(pu, pv, tu, tv, psp, tsp, lat, lev, dx, dt, dy);
    residual_k<<<(N4 + 255) / 256, 256>>>(psp, tsp, (float*)d_out);
}

// round 4
// speedup vs baseline: 1.3711x; 1.0412x over previous
#include <cuda_runtime.h>
#include <math.h>

#define T_DIM 4
#define C_DIM 13
#define H_DIM 361
#define W_DIM 720
#define HW    (H_DIM * W_DIM)        /* 259920  */
#define CHW   (C_DIM * HW)           /* 3378960 */
#define N2    (T_DIM * HW)           /* 1039680 */
#define W4    (W_DIM / 4)            /* 180     */
#define N4    (T_DIM * H_DIM * W4)   /* 259920  */

// Scratch (static device globals: allowed; no runtime allocation)
__device__ float  g_Up[N2];
__device__ float  g_Vp[N2];
__device__ float  g_Ut[N2];
__device__ float  g_Vt[N2];
__device__ float  g_lsp[N2];
__device__ float  g_lst[N2];
__device__ float  g_inv_adx[H_DIM];
__device__ float  g_consts[3];          // inv_dt, inv_2dt, inv_ady
__device__ double g_acc;
__device__ unsigned int g_bcount = 0;   // self-resetting via atomicInc wrap

__device__ __forceinline__ float4 LD4(const float* p) {
    return __ldg((const float4*)p);
}
// Streaming (evict-first) load: keeps the 216MB u/v stream from evicting the
// L2-resident scratch that residual_k needs right after.
__device__ __forceinline__ float4 LD4S(const float* p) {
    return __ldcs((const float4*)p);
}

// ---------------------------------------------------------------------------
// Kernel A: blockIdx.y selects work:
//   y = 0..3 : channel-weighted reduction of one tensor (13 float4 loads/thr)
//   y = 4    : log(sp) for both sources
// Block (0,0) additionally builds the reciprocal LUTs (accurate pole cos) and
// zeroes the accumulator — hidden under the memory stream.
// ---------------------------------------------------------------------------
__global__ void __launch_bounds__(256) reduce_k(
    const float* __restrict__ up, const float* __restrict__ vp,
    const float* __restrict__ ut, const float* __restrict__ vt,
    const float* __restrict__ spp, const float* __restrict__ spt,
    const float* __restrict__ lat, const float* __restrict__ lev,
    const float* __restrict__ dxp, const float* __restrict__ dtp,
    const float* __restrict__ dyp)
{
    const int ten = blockIdx.y;

    if (blockIdx.x == 0 && ten == 0) {
        for (int r = threadIdx.x; r < H_DIM; r += 256) {
            // Replicate JAX f32 sequence: ang = (lat * f32(pi)) / f32(180)
            float ang = (lat[r] * (float)M_PI) / 180.0f;
            // Accurate cos of the f32 angle (pole rows dominate the loss;
            // fast-math cos would destroy the ~4e-8 pole value)
            float cv  = (float)cos((double)ang);
            float mpl = (float)(M_PI * 6371000.0 / 180.0);
            float adx = dxp[0] * (mpl * cv);
            g_inv_adx[r] = (float)(1.0 / (double)adx);
        }
        if (threadIdx.x == 0) {
            float dtv = dtp[0];
            float mpl = (float)(M_PI * 6371000.0 / 180.0);
            float ady = dyp[0] * mpl;
            g_consts[0] = (float)(1.0 / (double)dtv);
            g_consts[1] = (float)(1.0 / (2.0 * (double)dtv));
            g_consts[2] = (float)(1.0 / (double)ady);
            g_acc = 0.0;
        }
    }

    int i = blockIdx.x * 256 + threadIdx.x;
    if (i >= N4) return;
    int w4 = i % W4;
    int hh = (i / W4) % H_DIM;
    int t  = i / (W4 * H_DIM);
    int base2 = t * HW  + hh * W_DIM + 4 * w4;

    if (ten == 4) {
        float4 s = LD4(spp + base2);
        float4 l;
        l.x = logf(s.x); l.y = logf(s.y); l.z = logf(s.z); l.w = logf(s.w);
        *(float4*)(g_lsp + base2) = l;
        s = LD4(spt + base2);
        l.x = logf(s.x); l.y = logf(s.y); l.z = logf(s.z); l.w = logf(s.w);
        *(float4*)(g_lst + base2) = l;
        return;
    }

    const float* __restrict__ src;
    float* dst;
    switch (ten) {
        case 0: src = up; dst = g_Up; break;
        case 1: src = vp; dst = g_Vp; break;
        case 2: src = ut; dst = g_Ut; break;
        default: src = vt; dst = g_Vt; break;
    }

    // delta-sigma pressure weights (constant per channel), f32 math like JAX
    float dpl[C_DIM];
    {
        dpl[0] = (__ldg(lev + 1) - __ldg(lev + 0)) * 100.0f;
        #pragma unroll
        for (int c = 1; c < C_DIM - 1; ++c)
            dpl[c] = (__ldg(lev + c + 1) - __ldg(lev + c - 1)) * 50.0f;
        dpl[C_DIM-1] = (__ldg(lev + C_DIM - 1) - __ldg(lev + C_DIM - 2)) * 100.0f;
    }

    int base5 = t * CHW + hh * W_DIM + 4 * w4;
    float4 acc = make_float4(0.f, 0.f, 0.f, 0.f);
    #pragma unroll
    for (int c = 0; c < C_DIM; ++c) {
        float4 a = LD4S(src + base5 + c * HW);   // streaming: evict-first
        float dp = dpl[c];
        acc.x = fmaf(dp, a.x, acc.x);
        acc.y = fmaf(dp, a.y, acc.y);
        acc.z = fmaf(dp, a.z, acc.z);
        acc.w = fmaf(dp, a.w, acc.w);
    }
    *(float4*)(dst + base2) = acc;
}

// ---------------------------------------------------------------------------
// Kernel B: 4-wide vectorized residual stencil; all loads hoisted into a
// gather struct so pred+target loads issue together (high MLP), then math.
// ---------------------------------------------------------------------------
struct Gather {
    float4 c, tn, u, v, ld, lu, vd, vu, s;
    float  lsl, lsr, ul, ur;
};

__device__ __forceinline__ Gather gather4(
    const float* __restrict__ ls, const float* __restrict__ Uf,
    const float* __restrict__ Vf, const float* __restrict__ sp,
    int base, int t, int hh, bool wlo, bool whi)
{
    Gather g;
    g.c = LD4(ls + base);
    g.u = LD4(Uf + base);
    g.v = LD4(Vf + base);
    g.s = LD4(sp + base);

    // time neighbor(s): tn holds (next - prev) pre-difference inputs
    if (t == 0)              { g.tn = LD4(ls + base + HW); }
    else if (t == T_DIM - 1) { g.tn = LD4(ls + base - HW); }
    else {
        float4 n = LD4(ls + base + HW);
        float4 p = LD4(ls + base - HW);
        g.tn.x = n.x - p.x; g.tn.y = n.y - p.y;
        g.tn.z = n.z - p.z; g.tn.w = n.w - p.w;
    }

    g.lsl = wlo ? 0.0f : __ldg(ls + base - 1);
    g.lsr = whi ? 0.0f : __ldg(ls + base + 4);
    g.ul  = wlo ? 0.0f : __ldg(Uf + base - 1);
    g.ur  = whi ? 0.0f : __ldg(Uf + base + 4);

    if (hh == 0) {
        g.ld = LD4(ls + base + W_DIM); g.lu = g.c;
        g.vd = LD4(Vf + base + W_DIM); g.vu = g.v;
    } else if (hh == H_DIM - 1) {
        g.ld = g.c; g.lu = LD4(ls + base - W_DIM);
        g.vd = g.v; g.vu = LD4(Vf + base - W_DIM);
    } else {
        g.ld = LD4(ls + base + W_DIM); g.lu = LD4(ls + base - W_DIM);
        g.vd = LD4(Vf + base + W_DIM); g.vu = LD4(Vf + base - W_DIM);
    }
    return g;
}

__device__ __forceinline__ float4 residual4(
    const Gather& g, int t, int hh, bool wlo, bool whi,
    float inv_dt, float inv_2dt, float inv_ady, float inv_adx)
{
    float4 r;
    if (t == 0) {
        r.x = (g.tn.x - g.c.x) * inv_dt; r.y = (g.tn.y - g.c.y) * inv_dt;
        r.z = (g.tn.z - g.c.z) * inv_dt; r.w = (g.tn.w - g.c.w) * inv_dt;
    } else if (t == T_DIM - 1) {
        r.x = (g.c.x - g.tn.x) * inv_dt; r.y = (g.c.y - g.tn.y) * inv_dt;
        r.z = (g.c.z - g.tn.z) * inv_dt; r.w = (g.c.w - g.tn.w) * inv_dt;
    } else {
        r.x = g.tn.x * inv_2dt; r.y = g.tn.y * inv_2dt;
        r.z = g.tn.z * inv_2dt; r.w = g.tn.w * inv_2dt;
    }

    float4 dlsx;
    dlsx.x = wlo ? (g.c.y - g.c.x) : (g.c.y - g.lsl) * 0.5f;
    dlsx.y = (g.c.z - g.c.x) * 0.5f;
    dlsx.z = (g.c.w - g.c.y) * 0.5f;
    dlsx.w = whi ? (g.c.w - g.c.z) : (g.lsr - g.c.z) * 0.5f;

    float4 dudx;
    dudx.x = wlo ? (g.u.y - g.u.x) : (g.u.y - g.ul) * 0.5f;
    dudx.y = (g.u.z - g.u.x) * 0.5f;
    dudx.z = (g.u.w - g.u.y) * 0.5f;
    dudx.w = whi ? (g.u.w - g.u.z) : (g.ur - g.u.z) * 0.5f;

    float hscale = (hh == 0 || hh == H_DIM - 1) ? 1.0f : 0.5f;
    float4 dlsy, dvdy;
    dlsy.x = (g.ld.x - g.lu.x) * hscale; dlsy.y = (g.ld.y - g.lu.y) * hscale;
    dlsy.z = (g.ld.z - g.lu.z) * hscale; dlsy.w = (g.ld.w - g.lu.w) * hscale;
    dvdy.x = (g.vd.x - g.vu.x) * hscale; dvdy.y = (g.vd.y - g.vu.y) * hscale;
    dvdy.z = (g.vd.z - g.vu.z) * hscale; dvdy.w = (g.vd.w - g.vu.w) * hscale;

    float4 out;
    float ix = fmaf(g.u.x, dlsx.x, dudx.x) * inv_adx
             + fmaf(g.v.x, dlsy.x, dvdy.x) * inv_ady;
    out.x = r.x + __fdividef(ix, g.s.x);
    float iy = fmaf(g.u.y, dlsx.y, dudx.y) * inv_adx
             + fmaf(g.v.y, dlsy.y, dvdy.y) * inv_ady;
    out.y = r.y + __fdividef(iy, g.s.y);
    float iz = fmaf(g.u.z, dlsx.z, dudx.z) * inv_adx
             + fmaf(g.v.z, dlsy.z, dvdy.z) * inv_ady;
    out.z = r.z + __fdividef(iz, g.s.z);
    float iw = fmaf(g.u.w, dlsx.w, dudx.w) * inv_adx
             + fmaf(g.v.w, dlsy.w, dvdy.w) * inv_ady;
    out.w = r.w + __fdividef(iw, g.s.w);
    return out;
}

__global__ void __launch_bounds__(256) residual_k(
    const float* __restrict__ spp, const float* __restrict__ spt,
    float* __restrict__ out)
{
    int i4 = blockIdx.x * 256 + threadIdx.x;
    float val = 0.0f;
    if (i4 < N4) {
        int w4 = i4 % W4;
        int hh = (i4 / W4) % H_DIM;
        int t  = i4 / (W4 * H_DIM);
        int base = t * HW + hh * W_DIM + 4 * w4;
        bool wlo = (w4 == 0), whi = (w4 == W4 - 1);

        float inv_dt  = g_consts[0];
        float inv_2dt = g_consts[1];
        float inv_ady = g_consts[2];
        float inv_adx = g_inv_adx[hh];

        // Issue ALL loads for both sources before the dependent math chains.
        Gather gp = gather4(g_lsp, g_Up, g_Vp, spp, base, t, hh, wlo, whi);
        Gather gt = gather4(g_lst, g_Ut, g_Vt, spt, base, t, hh, wlo, whi);

        float4 rp = residual4(gp, t, hh, wlo, whi, inv_dt, inv_2dt, inv_ady, inv_adx);
        float4 rt = residual4(gt, t, hh, wlo, whi, inv_dt, inv_2dt, inv_ady, inv_adx);
        float dx0 = rp.x - rt.x, dy0 = rp.y - rt.y;
        float dz0 = rp.z - rt.z, dw0 = rp.w - rt.w;
        val = dx0*dx0 + dy0*dy0 + dz0*dz0 + dw0*dw0;
    }

    #pragma unroll
    for (int o = 16; o > 0; o >>= 1)
        val += __shfl_down_sync(0xffffffffu, val, o);

    __shared__ float sw[8];
    __shared__ bool  isLast;
    int lane = threadIdx.x & 31;
    int wid  = threadIdx.x >> 5;
    if (lane == 0) sw[wid] = val;
    __syncthreads();
    if (wid == 0) {
        float v = (lane < 8) ? sw[lane] : 0.0f;
        #pragma unroll
        for (int o = 4; o > 0; o >>= 1)
            v += __shfl_down_sync(0xffffffffu, v, o);
        if (lane == 0) {
            atomicAdd(&g_acc, (double)v);
            __threadfence();
            unsigned done = atomicInc(&g_bcount, gridDim.x - 1);
            isLast = (done == gridDim.x - 1);   // wraps to 0 -> replay-safe
        }
    }
    __syncthreads();
    if (isLast && threadIdx.x == 0) {
        out[0] = (float)(g_acc / (double)N2);
    }
}

// ---------------------------------------------------------------------------
extern "C" void kernel_launch(void* const* d_in, const int* in_sizes, int n_in,
                              void* d_out, int out_size)
{
    const float* pu  = (const float*)d_in[0];
    const float* pv  = (const float*)d_in[1];
    const float* psp = (const float*)d_in[2];
    const float* tu  = (const float*)d_in[3];
    const float* tv  = (const float*)d_in[4];
    const float* tsp = (const float*)d_in[5];
    const float* lat = (const float*)d_in[6];
    const float* lev = (const float*)d_in[7];
    const float* dt  = (const float*)d_in[8];
    const float* dx  = (const float*)d_in[9];
    const float* dy  = (const float*)d_in[10];

    dim3 gridA((N4 + 255) / 256, 5);
    reduce_k<<<gridA, 256>>>(pu, pv, tu, tv, psp, tsp, lat, lev, dx, dt, dy);
    residual_k<<<(N4 + 255) / 256, 256>>>(psp, tsp, (float*)d_out);
}